// round 15
// baseline (speedup 1.0000x reference)
#include <cuda_runtime.h>
#include <cuda_bf16.h>
#include <cuda_fp16.h>
#include <math.h>
#include <cstdint>

// Problem dims
constexpr int BB = 64;    // batch
constexpr int TT = 256;   // time steps
constexpr int II = 256;   // input dim
constexpr int HH = 1024;  // hidden
constexpr int CC = 60;    // classes
constexpr int GG = 4096;  // 4*H
constexpr int NCTA = 128; // persistent CTAs; each owns 8 h-cols x 4 gates = 32 gate cols

// Dynamic SMEM layout (lstm_kernel): warp-per-chunk, single A buffer
constexpr int A_B = 0;         // 128KB: full h, 64 rows x 2048B, block-swizzled
                               // (overlaid by 4 x 9216B exchange regions post-MMA)
constexpr int WF = 131072;     // 64KB fragment-direct W (fp16)
constexpr int XP = 196608;     // 5120B xproj bounce [64][40] fp16
constexpr int SMEM_DYN = 201728;

// Dynamic SMEM layout (xproj_mma kernel): fp16 single-term
constexpr int XA = 0;          // 2 bufs x 16KB (128 rows x 64 fp16, SW128)
constexpr int XW = 32768;      // 32KB fragment-direct W_ih (fp16, 64 cols x 256 k)
constexpr int SMEM_X = 65536;

// Scratch (__device__ globals: allocation-free)
__device__ __half g_xp16[(size_t)TT * BB * GG];   // [t][b][g] fp16
__device__ __half g_hhi[2][BB * HH];              // h (fp16), ping-pong
__device__ __half g_hlo[2][BB * HH];              // h lo correction (final step only)
__device__ unsigned g_cnt[8];                     // striped step counters

// ---------------------------------------------------------------------------
// helpers
// ---------------------------------------------------------------------------
__device__ __forceinline__ uint32_t smem_u32(const void* p) {
    uint32_t a;
    asm("{ .reg .u64 t; cvta.to.shared.u64 t, %1; cvt.u32.u64 %0, t; }" : "=r"(a) : "l"(p));
    return a;
}
__device__ __forceinline__ void ldm_x4(uint32_t* r, uint32_t addr) {
    asm volatile("ldmatrix.sync.aligned.m8n8.x4.shared.b16 {%0,%1,%2,%3}, [%4];"
                 : "=r"(r[0]), "=r"(r[1]), "=r"(r[2]), "=r"(r[3]) : "r"(addr));
}
__device__ __forceinline__ void mma_f16(float* d, const uint32_t* a, uint32_t b0, uint32_t b1) {
    asm volatile(
        "mma.sync.aligned.m16n8k16.row.col.f32.f16.f16.f32 "
        "{%0,%1,%2,%3}, {%4,%5,%6,%7}, {%8,%9}, {%0,%1,%2,%3};"
        : "+f"(d[0]), "+f"(d[1]), "+f"(d[2]), "+f"(d[3])
        : "r"(a[0]), "r"(a[1]), "r"(a[2]), "r"(a[3]), "r"(b0), "r"(b1));
}
__device__ __forceinline__ uint32_t pack2h(__half a, __half b) {
    return (uint32_t)*(uint16_t*)&a | ((uint32_t)*(uint16_t*)&b << 16);
}
__device__ __forceinline__ float2 unpack2h(uint32_t v) {
    __half2 h = *(__half2*)&v;
    return __half22float2(h);
}
__device__ __forceinline__ void poll_ge(const unsigned* p, unsigned tgt) {
    unsigned v;
    do {
        asm volatile("ld.acquire.gpu.global.u32 %0, [%1];" : "=r"(v) : "l"(p) : "memory");
    } while (v < tgt);
}
// HW tanh: single MUFU op (sm_75+); sigmoid via tanh identity (1 MUFU + 1 FFMA)
__device__ __forceinline__ float ftanh(float x) {
    float y;
    asm("tanh.approx.f32 %0, %1;" : "=f"(y) : "f"(x));
    return y;
}
__device__ __forceinline__ float fsigmoid(float x) {
    return fmaf(ftanh(0.5f * x), 0.5f, 0.5f);
}

// ---------------------------------------------------------------------------
// Zero-init h buffers + striped step counters.
// ---------------------------------------------------------------------------
__global__ void zero_kernel() {
    int i = blockIdx.x * blockDim.x + threadIdx.x;
    if (i < BB * HH) {            // u32 words cover both ping-pong buffers
        ((unsigned*)g_hhi)[i] = 0u;
        ((unsigned*)g_hlo)[i] = 0u;
    }
    if (i < 8) g_cnt[i] = 0u;
}

// ---------------------------------------------------------------------------
// x_proj via fp16 single-term mma.sync; conv FUSED: stages inputs/W_ih from
// fp32 directly, converting to fp16 in-register. fp16 output.
// ---------------------------------------------------------------------------
__global__ __launch_bounds__(256, 1) void xproj_mma_kernel(
    const float* __restrict__ inp, const float* __restrict__ Wih,
    const float* __restrict__ bih, const float* __restrict__ bhh) {
    extern __shared__ char sm[];
    const int tid = threadIdx.x;
    const int lane = tid & 31;
    const int w = tid >> 5;
    const int n0 = blockIdx.x * 64;
    const uint32_t smb = smem_u32(sm);

    // W fragment fill (8192 u32, convert fp32 -> fp16)
    for (int idx = tid; idx < 8192; idx += 256) {
        int q = idx & 15, ln = (idx >> 4) & 31, ks = idx >> 9;
        int nt = q >> 1, rr = q & 1;
        int nl = nt * 8 + (ln >> 2);
        int k = ks * 16 + rr * 8 + (ln & 3) * 2;
        float2 wv = *(const float2*)(Wih + (n0 + nl) * II + k);
        ((uint32_t*)(sm + XW))[idx] = pack2h(__float2half(wv.x), __float2half(wv.y));
    }
    __syncthreads();

    const int grp = lane >> 2, tg = lane & 3;
    float bias0[8], bias1[8];
#pragma unroll
    for (int nt = 0; nt < 8; nt++) {
        int g = n0 + nt * 8 + tg * 2;
        bias0[nt] = bih[g] + bhh[g];
        bias1[nt] = bih[g + 1] + bhh[g + 1];
    }

    const int arow = w * 16 + (lane & 15);
    const int acol = (lane >> 4) * 16;

    for (int miter = 0; miter < 8; miter++) {
        const int m0 = (blockIdx.y * 8 + miter) * 128;

        float acc[8][4];
#pragma unroll
        for (int z = 0; z < 8; z++)
#pragma unroll
            for (int r = 0; r < 4; r++) acc[z][r] = 0.f;

        // prologue: chunk 0 -> buf 0 (load fp32, convert, store fp16)
#pragma unroll
        for (int i = 0; i < 4; i++) {
            int s = i * 256 + tid;
            int row = s >> 3, sb = s & 7;
            const float4* src = (const float4*)inp + (size_t)(m0 + row) * 64 + sb * 2;
            float4 f0 = src[0], f1 = src[1];
            uint4 v;
            v.x = pack2h(__float2half(f0.x), __float2half(f0.y));
            v.y = pack2h(__float2half(f0.z), __float2half(f0.w));
            v.z = pack2h(__float2half(f1.x), __float2half(f1.y));
            v.w = pack2h(__float2half(f1.z), __float2half(f1.w));
            int off = row * 128 + sb * 16;
            int sw = off ^ ((off >> 3) & 0x70);
            *(uint4*)(sm + XA + sw) = v;
        }
        __syncthreads();

        for (int ch = 0; ch < 4; ch++) {
            const int buf = ch & 1;
            uint4 ph[4];
            if (ch < 3) {
#pragma unroll
                for (int i = 0; i < 4; i++) {
                    int s = i * 256 + tid;
                    int row = s >> 3, sb = s & 7;
                    const float4* src = (const float4*)inp +
                        (size_t)(m0 + row) * 64 + (ch + 1) * 16 + sb * 2;
                    float4 f0 = src[0], f1 = src[1];
                    ph[i].x = pack2h(__float2half(f0.x), __float2half(f0.y));
                    ph[i].y = pack2h(__float2half(f0.z), __float2half(f0.w));
                    ph[i].z = pack2h(__float2half(f1.x), __float2half(f1.y));
                    ph[i].w = pack2h(__float2half(f1.z), __float2half(f1.w));
                }
            }
            const uint32_t ab = smb + XA + buf * 16384;
#pragma unroll
            for (int kl = 0; kl < 4; kl++) {
                const int ks = ch * 4 + kl;
                int off = arow * 128 + kl * 32 + acol;
                int sw = off ^ ((off >> 3) & 0x70);
                uint32_t ah[4];
                ldm_x4(ah, ab + sw);
                const uint4* wh4 = (const uint4*)(sm + XW) + (ks * 32 + lane) * 4;
#pragma unroll
                for (int q4 = 0; q4 < 4; q4++) {
                    uint4 bh = wh4[q4];
                    mma_f16(acc[2 * q4], ah, bh.x, bh.y);
                    mma_f16(acc[2 * q4 + 1], ah, bh.z, bh.w);
                }
            }
            if (ch < 3) {
                char* dh = sm + XA + (buf ^ 1) * 16384;
#pragma unroll
                for (int i = 0; i < 4; i++) {
                    int s = i * 256 + tid;
                    int row = s >> 3, sb = s & 7;
                    int off = row * 128 + sb * 16;
                    int sw = off ^ ((off >> 3) & 0x70);
                    *(uint4*)(dh + sw) = ph[i];
                }
            }
            __syncthreads();
        }

        int r0 = m0 + w * 16 + grp;
        int r1 = r0 + 8;
        size_t ob0 = ((size_t)(r0 & 255) * BB + (r0 >> 8)) * GG;
        size_t ob1 = ((size_t)(r1 & 255) * BB + (r1 >> 8)) * GG;
#pragma unroll
        for (int nt = 0; nt < 8; nt++) {
            int g = n0 + nt * 8 + tg * 2;
            *(uint32_t*)(g_xp16 + ob0 + g) =
                pack2h(__float2half(acc[nt][0] + bias0[nt]), __float2half(acc[nt][1] + bias1[nt]));
            *(uint32_t*)(g_xp16 + ob1 + g) =
                pack2h(__float2half(acc[nt][2] + bias0[nt]), __float2half(acc[nt][3] + bias1[nt]));
        }
    }
}

// ---------------------------------------------------------------------------
// Persistent LSTM recurrence: 128 CTAs x 256 thr, fp16 single-term.
// R13 warp tile (r32/c32/kk256) + NEW warp-private A staging: each warp
// stages only its own 16KB tile (rows rg*32..+32 x k-chunk kh) and proceeds
// after __syncwarp -- no cross-warp staging barrier. 3 syncthreads/step.
// ---------------------------------------------------------------------------
__global__ __launch_bounds__(256, 1) void lstm_kernel(const float* __restrict__ Whh) {
    extern __shared__ char sm[];
    const int tid = threadIdx.x;
    const int lane = tid & 31;
    const int w = tid >> 5;
    const int rg = w >> 2, kh = w & 3;
    const int hc0 = blockIdx.x * 8;
    const uint32_t smb = smem_u32(sm);

    // ---- one-time: W fragment fill (fp16, fragment-direct layout) ----
    for (int idx = tid; idx < 16384; idx += 256) {
        int r = idx & 3, ln = (idx >> 2) & 31, ks = (idx >> 7) & 63, nhh = idx >> 13;
        int nt = r >> 1;
        int kk = (r & 1) * 8 + (ln & 3) * 2;
        int nl = nhh * 16 + nt * 8 + (ln >> 2);
        int k = ks * 16 + kk;
        int gr = (nl >> 3) * 1024 + hc0 + (nl & 7);
        __half h0 = __float2half(Whh[gr * 1024 + k]);
        __half h1 = __float2half(Whh[gr * 1024 + k + 1]);
        ((uint32_t*)(sm + WF))[idx] = pack2h(h0, h1);
    }
    __syncthreads();

    // xproj loader constants: thread loads (b=tid&63, q=tid>>6) 8 halves = uint4
    const int xlb = tid & 63, xlq = tid >> 6;
    const __half* xsrc0 = g_xp16 + (size_t)xlb * GG + xlq * HH + hc0;
    __half* const xps = (__half*)(sm + XP);     // [64][40] halves

    // warp-private staging constants: tile rows rg*32..+32, segs kh*32..+32
    // per row: one coalesced 512B warp load, seg = kh*32 + lane
    const int sseg_block = (kh * 4 + (lane >> 3)) * 128;   // byte offset of 128B block
    const int sinner = lane & 7;

    // A ldmatrix per-lane constants: rows r0 = rg*32 + (lane&15), r1 = r0+16
    const int ar0 = rg * 32 + (lane & 15);
    const int ar1 = ar0 + 16;
    const int ahalf = lane >> 4;                // k-half within kstep

    // W fragment bases for this warp's chunk (uint4 idx = nh*2048 + ks*32 + lane)
    const uint4* wf0 = (const uint4*)(sm + WF) + (kh * 16) * 32 + lane;
    const uint4* wf1 = wf0 + 2048;

    // epilogue ownership: this thread handles states (b, ej) and (b, ej+4)
    const int eb = tid & 63, ej = tid >> 6;
    float c0 = 0.f, c1 = 0.f;

    for (int t = 0; t < TT; t++) {
        const uint4* gh = (const uint4*)g_hhi[t & 1];

        // stage this CTA's xproj slice (coalesced, h-independent): BEFORE poll
        {
            uint4 xv = *(const uint4*)(xsrc0 + (size_t)t * BB * GG);
            *(uint4*)(xps + xlb * 40 + xlq * 8) = xv;
        }

        // wait for all CTAs to have finished step t-1 (each warp independently)
        if (t) {
            if (lane < 8) poll_ge(&g_cnt[lane], 16u * (unsigned)t);
            __syncwarp();
        }

        // warp-private A staging: 32 rows x 512B, batched 8 for MLP
#pragma unroll
        for (int i0 = 0; i0 < 32; i0 += 8) {
            uint4 v[8];
#pragma unroll
            for (int i = 0; i < 8; i++) {
                int row = rg * 32 + i0 + i;
                v[i] = __ldcg(gh + row * 128 + kh * 32 + lane);
            }
#pragma unroll
            for (int i = 0; i < 8; i++) {
                int row = rg * 32 + i0 + i;
                *(uint4*)(sm + A_B + row * 2048 + sseg_block + ((sinner ^ (row & 7)) << 4)) = v[i];
            }
        }
        __syncwarp();

        // MMA: 16 ksteps of this warp's chunk; 8 independent chains
        float acc[8][4];
#pragma unroll
        for (int z = 0; z < 8; z++)
#pragma unroll
            for (int r = 0; r < 4; r++) acc[z][r] = 0.f;
#pragma unroll
        for (int kl = 0; kl < 16; kl++) {
            int seg = kh * 32 + kl * 2 + ahalf;
            int block = seg >> 3, inner = seg & 7;
            uint32_t a0[4], a1[4];
            ldm_x4(a0, smb + A_B + ar0 * 2048 + block * 128 + ((inner ^ (ar0 & 7)) << 4));
            ldm_x4(a1, smb + A_B + ar1 * 2048 + block * 128 + ((inner ^ (ar1 & 7)) << 4));
            uint4 b0 = wf0[kl * 32];
            uint4 b1 = wf1[kl * 32];
            mma_f16(acc[0], a0, b0.x, b0.y);
            mma_f16(acc[1], a0, b0.z, b0.w);
            mma_f16(acc[2], a0, b1.x, b1.y);
            mma_f16(acc[3], a0, b1.z, b1.w);
            mma_f16(acc[4], a1, b0.x, b0.y);
            mma_f16(acc[5], a1, b0.z, b0.w);
            mma_f16(acc[6], a1, b1.x, b1.y);
            mma_f16(acc[7], a1, b1.z, b1.w);
        }
        __syncthreads();   // all A reads done -> safe to overlay exchange regions

        // epilogue: write partials to region kh  [32 cols][stride 72]
        {
            float* sgk = (float*)(sm + kh * 9216);
            int grp = lane >> 2, tg = lane & 3;
#pragma unroll
            for (int nj = 0; nj < 4; nj++) {
                int col = nj * 8 + tg * 2;
                int row0 = rg * 32 + grp;
                int row1 = row0 + 16;
                sgk[col * 72 + row0] = acc[nj][0];
                sgk[(col + 1) * 72 + row0] = acc[nj][1];
                sgk[col * 72 + row0 + 8] = acc[nj][2];
                sgk[(col + 1) * 72 + row0 + 8] = acc[nj][3];
                sgk[col * 72 + row1] = acc[4 + nj][0];
                sgk[(col + 1) * 72 + row1] = acc[4 + nj][1];
                sgk[col * 72 + row1 + 8] = acc[4 + nj][2];
                sgk[(col + 1) * 72 + row1 + 8] = acc[4 + nj][3];
            }
        }
        __syncthreads();

        // pointwise update (HW tanh): sum 4 k-partials; 2 states per thread
        {
            const float* s0 = (const float*)(sm);
            const float* s1 = (const float*)(sm + 9216);
            const float* s2 = (const float*)(sm + 18432);
            const float* s3 = (const float*)(sm + 27648);
            __half* hh = g_hhi[(t + 1) & 1];
            __half* hl = g_hlo[(t + 1) & 1];
            const bool last = (t == TT - 1);
            const __half* xb = xps + eb * 40;
#pragma unroll
            for (int st = 0; st < 2; st++) {
                int j = ej + st * 4;
                int o0 = (0 + j) * 72 + eb, o1 = (8 + j) * 72 + eb;
                int o2 = (16 + j) * 72 + eb, o3 = (24 + j) * 72 + eb;
                float iv = s0[o0] + s1[o0] + s2[o0] + s3[o0] + __half2float(xb[0 * 8 + j]);
                float fv = s0[o1] + s1[o1] + s2[o1] + s3[o1] + __half2float(xb[1 * 8 + j]);
                float gv = s0[o2] + s1[o2] + s2[o2] + s3[o2] + __half2float(xb[2 * 8 + j]);
                float ov = s0[o3] + s1[o3] + s2[o3] + s3[o3] + __half2float(xb[3 * 8 + j]);
                float& cs = st ? c1 : c0;
                float cn = fsigmoid(fv) * cs + fsigmoid(iv) * ftanh(gv);
                cs = cn;
                float hn = fsigmoid(ov) * ftanh(cn);
                __half hbb = __float2half(hn);
                hh[eb * HH + hc0 + j] = hbb;
                if (last) hl[eb * HH + hc0 + j] = __float2half(hn - __half2float(hbb));
            }
        }
        __syncthreads();
        if (tid == 0) {
            __threadfence();                           // order h stores (gpu scope)
            atomicAdd(&g_cnt[blockIdx.x & 7], 1u);     // striped step-done signal
        }
    }
}

// ---------------------------------------------------------------------------
// logits = h_last @ fc_w^T + fc_b; out = log_softmax.  grid=64, block=256.
// h_last = g_hhi[0] + g_hlo[0]  (full precision at the final step)
// ---------------------------------------------------------------------------
__global__ __launch_bounds__(256) void fc_kernel(const float* __restrict__ fcw,
                                                 const float* __restrict__ fcb,
                                                 float* __restrict__ out) {
    __shared__ float sh[HH];
    __shared__ float sl[64];
    __shared__ float s_red[2];
    int b = blockIdx.x;
    int tid = threadIdx.x;
    int w = tid >> 5, lane = tid & 31;

    {
        uint2 vh = ((const uint2*)(g_hhi[0] + b * HH))[tid];
        uint2 vl = ((const uint2*)(g_hlo[0] + b * HH))[tid];
        float2 h0 = unpack2h(vh.x), h1 = unpack2h(vh.y);
        float2 l0 = unpack2h(vl.x), l1 = unpack2h(vl.y);
        float4 f = make_float4(h0.x + l0.x, h0.y + l0.y, h1.x + l1.x, h1.y + l1.y);
        ((float4*)sh)[tid] = f;
    }
    __syncthreads();

#pragma unroll
    for (int cc = 0; cc < 8; cc++) {
        int c = w * 8 + cc;
        float s = 0.f;
        if (c < CC) {
            const float* wr = fcw + c * HH;
#pragma unroll 8
            for (int i = 0; i < 32; i++) {
                int k = i * 32 + lane;
                s += sh[k] * wr[k];
            }
        }
#pragma unroll
        for (int off = 16; off > 0; off >>= 1) s += __shfl_xor_sync(0xFFFFFFFF, s, off);
        if (lane == 0) sl[c] = (c < CC) ? s + fcb[c] : -1e30f;
    }
    __syncthreads();

    if (w == 0) {
        float v0 = sl[lane], v1 = sl[lane + 32];
        float m = fmaxf(v0, v1);
#pragma unroll
        for (int off = 16; off > 0; off >>= 1) m = fmaxf(m, __shfl_xor_sync(0xFFFFFFFF, m, off));
        float e = expf(v0 - m) + expf(v1 - m);
#pragma unroll
        for (int off = 16; off > 0; off >>= 1) e += __shfl_xor_sync(0xFFFFFFFF, e, off);
        if (lane == 0) { s_red[0] = m; s_red[1] = logf(e); }
    }
    __syncthreads();
    if (tid < CC) out[b * CC + tid] = sl[tid] - s_red[0] - s_red[1];
}

// ---------------------------------------------------------------------------
extern "C" void kernel_launch(void* const* d_in, const int* in_sizes, int n_in,
                              void* d_out, int out_size) {
    const float* inp = (const float*)d_in[0];   // [B,T,I]
    const float* Wih = (const float*)d_in[1];   // [4H,I]
    const float* Whh = (const float*)d_in[2];   // [4H,H]
    const float* bih = (const float*)d_in[3];   // [4H]
    const float* bhh = (const float*)d_in[4];   // [4H]
    const float* fcw = (const float*)d_in[5];   // [C,H]
    const float* fcb = (const float*)d_in[6];   // [C]
    float* out = (float*)d_out;                 // [B,C]

    cudaFuncSetAttribute(lstm_kernel, cudaFuncAttributeMaxDynamicSharedMemorySize, SMEM_DYN);
    cudaFuncSetAttribute(xproj_mma_kernel, cudaFuncAttributeMaxDynamicSharedMemorySize, SMEM_X);

    zero_kernel<<<512, 256>>>();

    dim3 gx(64, 16);
    xproj_mma_kernel<<<gx, 256, SMEM_X>>>(inp, Wih, bih, bhh);

    lstm_kernel<<<NCTA, 256, SMEM_DYN>>>(Whh);

    fc_kernel<<<BB, 64 * 4>>>(fcw, fcb, out);
}

// round 16
// speedup vs baseline: 1.5474x; 1.5474x over previous
#include <cuda_runtime.h>
#include <cuda_bf16.h>
#include <cuda_fp16.h>
#include <math.h>
#include <cstdint>

// Problem dims
constexpr int BB = 64;    // batch
constexpr int TT = 256;   // time steps
constexpr int II = 256;   // input dim
constexpr int HH = 1024;  // hidden
constexpr int CC = 60;    // classes
constexpr int GG = 4096;  // 4*H
constexpr int NCTA = 128; // persistent CTAs; each owns 8 h-cols x 4 gates = 32 gate cols

// Dynamic SMEM layout (lstm_kernel): warp-per-chunk, single A buffer
constexpr int A_B = 0;         // 128KB: full h, 64 rows x 2048B, block-swizzled
                               // (overlaid by 4 x 9216B exchange regions post-MMA)
constexpr int WF = 131072;     // 64KB fragment-direct W (fp16)
constexpr int XP = 196608;     // 5120B xproj bounce [64][40] fp16
constexpr int SMEM_DYN = 201728;

// Dynamic SMEM layout (xproj_mma kernel): fp16 single-term
constexpr int XA = 0;          // 2 bufs x 16KB (128 rows x 64 fp16, SW128)
constexpr int XW = 32768;      // 32KB fragment-direct W_ih (fp16, 64 cols x 256 k)
constexpr int SMEM_X = 65536;

// Scratch (__device__ globals: allocation-free)
__device__ __half g_xp16[(size_t)TT * BB * GG];   // [t][b][g] fp16
__device__ __half g_hhi[2][BB * HH];              // h (fp16), ping-pong
__device__ __half g_hlo[2][BB * HH];              // h lo correction (final step only)
__device__ __half g_xh[BB * TT * II];             // inputs fp16  [(b*T+t)][i]
__device__ __half g_wih[GG * II];                 // W_ih fp16 [g][i]
__device__ unsigned g_cnt[8];                     // striped step counters

// ---------------------------------------------------------------------------
// helpers
// ---------------------------------------------------------------------------
__device__ __forceinline__ uint32_t smem_u32(const void* p) {
    uint32_t a;
    asm("{ .reg .u64 t; cvta.to.shared.u64 t, %1; cvt.u32.u64 %0, t; }" : "=r"(a) : "l"(p));
    return a;
}
__device__ __forceinline__ void ldm_x4(uint32_t* r, uint32_t addr) {
    asm volatile("ldmatrix.sync.aligned.m8n8.x4.shared.b16 {%0,%1,%2,%3}, [%4];"
                 : "=r"(r[0]), "=r"(r[1]), "=r"(r[2]), "=r"(r[3]) : "r"(addr));
}
__device__ __forceinline__ void mma_f16(float* d, const uint32_t* a, uint32_t b0, uint32_t b1) {
    asm volatile(
        "mma.sync.aligned.m16n8k16.row.col.f32.f16.f16.f32 "
        "{%0,%1,%2,%3}, {%4,%5,%6,%7}, {%8,%9}, {%0,%1,%2,%3};"
        : "+f"(d[0]), "+f"(d[1]), "+f"(d[2]), "+f"(d[3])
        : "r"(a[0]), "r"(a[1]), "r"(a[2]), "r"(a[3]), "r"(b0), "r"(b1));
}
__device__ __forceinline__ uint32_t pack2h(__half a, __half b) {
    return (uint32_t)*(uint16_t*)&a | ((uint32_t)*(uint16_t*)&b << 16);
}
__device__ __forceinline__ float2 unpack2h(uint32_t v) {
    __half2 h = *(__half2*)&v;
    return __half22float2(h);
}
__device__ __forceinline__ void poll_ge(const unsigned* p, unsigned tgt) {
    unsigned v;
    do {
        asm volatile("ld.acquire.gpu.global.u32 %0, [%1];" : "=r"(v) : "l"(p) : "memory");
    } while (v < tgt);
}
// HW tanh: single MUFU op (sm_75+); sigmoid via tanh identity (1 MUFU + 1 FFMA)
__device__ __forceinline__ float ftanh(float x) {
    float y;
    asm("tanh.approx.f32 %0, %1;" : "=f"(y) : "f"(x));
    return y;
}
__device__ __forceinline__ float fsigmoid(float x) {
    return fmaf(ftanh(0.5f * x), 0.5f, 0.5f);
}

// ---------------------------------------------------------------------------
// Zero-init h buffers + striped step counters.
// ---------------------------------------------------------------------------
__global__ void zero_kernel() {
    int i = blockIdx.x * blockDim.x + threadIdx.x;
    if (i < BB * HH) {            // u32 words cover both ping-pong buffers
        ((unsigned*)g_hhi)[i] = 0u;
        ((unsigned*)g_hlo)[i] = 0u;
    }
    if (i < 8) g_cnt[i] = 0u;
}

// ---------------------------------------------------------------------------
// Convert inputs and W_ih to fp16 (row-major, same layout).
// ---------------------------------------------------------------------------
__global__ void conv_kernel(const float* __restrict__ inp, const float* __restrict__ Wih) {
    int stride = gridDim.x * blockDim.x;
    int i0 = blockIdx.x * blockDim.x + threadIdx.x;
    for (int i = i0; i < 1048576; i += stride) {       // inputs: 1M float4
        float4 v = ((const float4*)inp)[i];
        uint2 h = make_uint2(pack2h(__float2half(v.x), __float2half(v.y)),
                             pack2h(__float2half(v.z), __float2half(v.w)));
        ((uint2*)g_xh)[i] = h;
    }
    for (int i = i0; i < 262144; i += stride) {        // W_ih: 256K float4
        float4 v = ((const float4*)Wih)[i];
        uint2 h = make_uint2(pack2h(__float2half(v.x), __float2half(v.y)),
                             pack2h(__float2half(v.z), __float2half(v.w)));
        ((uint2*)g_wih)[i] = h;
    }
}

// ---------------------------------------------------------------------------
// x_proj via fp16 single-term mma.sync (proven round 9); fp16 output.
// ---------------------------------------------------------------------------
__global__ __launch_bounds__(256, 1) void xproj_mma_kernel(
    const float* __restrict__ bih, const float* __restrict__ bhh) {
    extern __shared__ char sm[];
    const int tid = threadIdx.x;
    const int lane = tid & 31;
    const int w = tid >> 5;
    const int n0 = blockIdx.x * 64;
    const uint32_t smb = smem_u32(sm);

    // W fragment fill (8192 u32, fp16)
    for (int idx = tid; idx < 8192; idx += 256) {
        int q = idx & 15, ln = (idx >> 4) & 31, ks = idx >> 9;
        int nt = q >> 1, rr = q & 1;
        int nl = nt * 8 + (ln >> 2);
        int k = ks * 16 + rr * 8 + (ln & 3) * 2;
        ((uint32_t*)(sm + XW))[idx] = *(const uint32_t*)(g_wih + (n0 + nl) * II + k);
    }
    __syncthreads();

    const int grp = lane >> 2, tg = lane & 3;
    float bias0[8], bias1[8];
#pragma unroll
    for (int nt = 0; nt < 8; nt++) {
        int g = n0 + nt * 8 + tg * 2;
        bias0[nt] = bih[g] + bhh[g];
        bias1[nt] = bih[g + 1] + bhh[g + 1];
    }

    const int arow = w * 16 + (lane & 15);
    const int acol = (lane >> 4) * 16;

    for (int miter = 0; miter < 8; miter++) {
        const int m0 = (blockIdx.y * 8 + miter) * 128;

        float acc[8][4];
#pragma unroll
        for (int z = 0; z < 8; z++)
#pragma unroll
            for (int r = 0; r < 4; r++) acc[z][r] = 0.f;

        // prologue: chunk 0 -> buf 0 (4 x 16B segments per thread)
#pragma unroll
        for (int i = 0; i < 4; i++) {
            int s = i * 256 + tid;
            int row = s >> 3, sb = s & 7;
            uint4 v = ((const uint4*)g_xh)[(m0 + row) * 32 + sb];
            int off = row * 128 + sb * 16;
            int sw = off ^ ((off >> 3) & 0x70);
            *(uint4*)(sm + XA + sw) = v;
        }
        __syncthreads();

        for (int ch = 0; ch < 4; ch++) {
            const int buf = ch & 1;
            uint4 ph[4];
            if (ch < 3) {
#pragma unroll
                for (int i = 0; i < 4; i++) {
                    int s = i * 256 + tid;
                    int row = s >> 3, sb = s & 7;
                    ph[i] = ((const uint4*)g_xh)[(m0 + row) * 32 + (ch + 1) * 8 + sb];
                }
            }
            const uint32_t ab = smb + XA + buf * 16384;
#pragma unroll
            for (int kl = 0; kl < 4; kl++) {
                const int ks = ch * 4 + kl;
                int off = arow * 128 + kl * 32 + acol;
                int sw = off ^ ((off >> 3) & 0x70);
                uint32_t ah[4];
                ldm_x4(ah, ab + sw);
                const uint4* wh4 = (const uint4*)(sm + XW) + (ks * 32 + lane) * 4;
#pragma unroll
                for (int q4 = 0; q4 < 4; q4++) {
                    uint4 bh = wh4[q4];
                    mma_f16(acc[2 * q4], ah, bh.x, bh.y);
                    mma_f16(acc[2 * q4 + 1], ah, bh.z, bh.w);
                }
            }
            if (ch < 3) {
                char* dh = sm + XA + (buf ^ 1) * 16384;
#pragma unroll
                for (int i = 0; i < 4; i++) {
                    int s = i * 256 + tid;
                    int row = s >> 3, sb = s & 7;
                    int off = row * 128 + sb * 16;
                    int sw = off ^ ((off >> 3) & 0x70);
                    *(uint4*)(dh + sw) = ph[i];
                }
            }
            __syncthreads();
        }

        int r0 = m0 + w * 16 + grp;
        int r1 = r0 + 8;
        size_t ob0 = ((size_t)(r0 & 255) * BB + (r0 >> 8)) * GG;
        size_t ob1 = ((size_t)(r1 & 255) * BB + (r1 >> 8)) * GG;
#pragma unroll
        for (int nt = 0; nt < 8; nt++) {
            int g = n0 + nt * 8 + tg * 2;
            *(uint32_t*)(g_xp16 + ob0 + g) =
                pack2h(__float2half(acc[nt][0] + bias0[nt]), __float2half(acc[nt][1] + bias1[nt]));
            *(uint32_t*)(g_xp16 + ob1 + g) =
                pack2h(__float2half(acc[nt][2] + bias0[nt]), __float2half(acc[nt][3] + bias1[nt]));
        }
    }
}

// ---------------------------------------------------------------------------
// Persistent LSTM recurrence: 128 CTAs x 256 thr, fp16 single-term.
// R14 base (striped counters, fp16 xproj bounce) + warp-private A staging:
// each warp stages only its own 16KB tile (rows rg*32..+32 x k-chunk kh) and
// proceeds after __syncwarp -- no cross-warp staging barrier.
// ---------------------------------------------------------------------------
__global__ __launch_bounds__(256, 1) void lstm_kernel(const float* __restrict__ Whh) {
    extern __shared__ char sm[];
    const int tid = threadIdx.x;
    const int lane = tid & 31;
    const int w = tid >> 5;
    const int rg = w >> 2, kh = w & 3;
    const int hc0 = blockIdx.x * 8;
    const uint32_t smb = smem_u32(sm);

    // ---- one-time: W fragment fill (fp16, fragment-direct layout) ----
    for (int idx = tid; idx < 16384; idx += 256) {
        int r = idx & 3, ln = (idx >> 2) & 31, ks = (idx >> 7) & 63, nhh = idx >> 13;
        int nt = r >> 1;
        int kk = (r & 1) * 8 + (ln & 3) * 2;
        int nl = nhh * 16 + nt * 8 + (ln >> 2);
        int k = ks * 16 + kk;
        int gr = (nl >> 3) * 1024 + hc0 + (nl & 7);
        __half h0 = __float2half(Whh[gr * 1024 + k]);
        __half h1 = __float2half(Whh[gr * 1024 + k + 1]);
        ((uint32_t*)(sm + WF))[idx] = pack2h(h0, h1);
    }
    __syncthreads();

    // xproj loader constants: thread loads (b=tid&63, q=tid>>6) 8 halves = uint4
    const int xlb = tid & 63, xlq = tid >> 6;
    const __half* xsrc0 = g_xp16 + (size_t)xlb * GG + xlq * HH + hc0;
    __half* const xps = (__half*)(sm + XP);     // [64][40] halves

    // warp-private staging constants: tile rows rg*32..+32, segs kh*32..+32
    const int sseg_block = (kh * 4 + (lane >> 3)) * 128;   // byte offset of 128B block
    const int sinner = lane & 7;

    // A ldmatrix per-lane constants: rows r0 = rg*32 + (lane&15), r1 = r0+16
    const int ar0 = rg * 32 + (lane & 15);
    const int ar1 = ar0 + 16;
    const int ahalf = lane >> 4;                // k-half within kstep

    // W fragment bases for this warp's chunk (uint4 idx = nh*2048 + ks*32 + lane)
    const uint4* wf0 = (const uint4*)(sm + WF) + (kh * 16) * 32 + lane;
    const uint4* wf1 = wf0 + 2048;

    // epilogue ownership: this thread handles states (b, ej) and (b, ej+4)
    const int eb = tid & 63, ej = tid >> 6;
    float c0 = 0.f, c1 = 0.f;

    for (int t = 0; t < TT; t++) {
        const uint4* gh = (const uint4*)g_hhi[t & 1];

        // stage this CTA's xproj slice (coalesced, h-independent): BEFORE poll
        {
            uint4 xv = *(const uint4*)(xsrc0 + (size_t)t * BB * GG);
            *(uint4*)(xps + xlb * 40 + xlq * 8) = xv;
        }

        // wait for all CTAs to have finished step t-1 (each warp independently)
        if (t) {
            if (lane < 8) poll_ge(&g_cnt[lane], 16u * (unsigned)t);
            __syncwarp();
        }

        // warp-private A staging: 32 rows x 512B (this warp's tile only)
#pragma unroll
        for (int i0 = 0; i0 < 32; i0 += 8) {
            uint4 v[8];
#pragma unroll
            for (int i = 0; i < 8; i++) {
                int row = rg * 32 + i0 + i;
                v[i] = __ldcg(gh + row * 128 + kh * 32 + lane);
            }
#pragma unroll
            for (int i = 0; i < 8; i++) {
                int row = rg * 32 + i0 + i;
                *(uint4*)(sm + A_B + row * 2048 + sseg_block + ((sinner ^ (row & 7)) << 4)) = v[i];
            }
        }
        __syncwarp();

        // MMA: 16 ksteps of this warp's chunk; 8 independent chains
        float acc[8][4];
#pragma unroll
        for (int z = 0; z < 8; z++)
#pragma unroll
            for (int r = 0; r < 4; r++) acc[z][r] = 0.f;
#pragma unroll
        for (int kl = 0; kl < 16; kl++) {
            int seg = kh * 32 + kl * 2 + ahalf;
            int block = seg >> 3, inner = seg & 7;
            uint32_t a0[4], a1[4];
            ldm_x4(a0, smb + A_B + ar0 * 2048 + block * 128 + ((inner ^ (ar0 & 7)) << 4));
            ldm_x4(a1, smb + A_B + ar1 * 2048 + block * 128 + ((inner ^ (ar1 & 7)) << 4));
            uint4 b0 = wf0[kl * 32];
            uint4 b1 = wf1[kl * 32];
            mma_f16(acc[0], a0, b0.x, b0.y);
            mma_f16(acc[1], a0, b0.z, b0.w);
            mma_f16(acc[2], a0, b1.x, b1.y);
            mma_f16(acc[3], a0, b1.z, b1.w);
            mma_f16(acc[4], a1, b0.x, b0.y);
            mma_f16(acc[5], a1, b0.z, b0.w);
            mma_f16(acc[6], a1, b1.x, b1.y);
            mma_f16(acc[7], a1, b1.z, b1.w);
        }
        __syncthreads();   // all A reads done -> safe to overlay exchange regions

        // epilogue: write partials to region kh  [32 cols][stride 72]
        {
            float* sgk = (float*)(sm + kh * 9216);
            int grp = lane >> 2, tg = lane & 3;
#pragma unroll
            for (int nj = 0; nj < 4; nj++) {
                int col = nj * 8 + tg * 2;
                int row0 = rg * 32 + grp;
                int row1 = row0 + 16;
                sgk[col * 72 + row0] = acc[nj][0];
                sgk[(col + 1) * 72 + row0] = acc[nj][1];
                sgk[col * 72 + row0 + 8] = acc[nj][2];
                sgk[(col + 1) * 72 + row0 + 8] = acc[nj][3];
                sgk[col * 72 + row1] = acc[4 + nj][0];
                sgk[(col + 1) * 72 + row1] = acc[4 + nj][1];
                sgk[col * 72 + row1 + 8] = acc[4 + nj][2];
                sgk[(col + 1) * 72 + row1 + 8] = acc[4 + nj][3];
            }
        }
        __syncthreads();

        // pointwise update (HW tanh): sum 4 k-partials; 2 states per thread
        {
            const float* s0 = (const float*)(sm);
            const float* s1 = (const float*)(sm + 9216);
            const float* s2 = (const float*)(sm + 18432);
            const float* s3 = (const float*)(sm + 27648);
            __half* hh = g_hhi[(t + 1) & 1];
            __half* hl = g_hlo[(t + 1) & 1];
            const bool last = (t == TT - 1);
            const __half* xb = xps + eb * 40;
#pragma unroll
            for (int st = 0; st < 2; st++) {
                int j = ej + st * 4;
                int o0 = (0 + j) * 72 + eb, o1 = (8 + j) * 72 + eb;
                int o2 = (16 + j) * 72 + eb, o3 = (24 + j) * 72 + eb;
                float iv = s0[o0] + s1[o0] + s2[o0] + s3[o0] + __half2float(xb[0 * 8 + j]);
                float fv = s0[o1] + s1[o1] + s2[o1] + s3[o1] + __half2float(xb[1 * 8 + j]);
                float gv = s0[o2] + s1[o2] + s2[o2] + s3[o2] + __half2float(xb[2 * 8 + j]);
                float ov = s0[o3] + s1[o3] + s2[o3] + s3[o3] + __half2float(xb[3 * 8 + j]);
                float& cs = st ? c1 : c0;
                float cn = fsigmoid(fv) * cs + fsigmoid(iv) * ftanh(gv);
                cs = cn;
                float hn = fsigmoid(ov) * ftanh(cn);
                __half hbb = __float2half(hn);
                hh[eb * HH + hc0 + j] = hbb;
                if (last) hl[eb * HH + hc0 + j] = __float2half(hn - __half2float(hbb));
            }
        }
        __syncthreads();
        if (tid == 0) {
            __threadfence();                           // order h stores (gpu scope)
            atomicAdd(&g_cnt[blockIdx.x & 7], 1u);     // striped step-done signal
        }
    }
}

// ---------------------------------------------------------------------------
// logits = h_last @ fc_w^T + fc_b; out = log_softmax.  grid=64, block=256.
// h_last = g_hhi[0] + g_hlo[0]  (full precision at the final step)
// ---------------------------------------------------------------------------
__global__ __launch_bounds__(256) void fc_kernel(const float* __restrict__ fcw,
                                                 const float* __restrict__ fcb,
                                                 float* __restrict__ out) {
    __shared__ float sh[HH];
    __shared__ float sl[64];
    __shared__ float s_red[2];
    int b = blockIdx.x;
    int tid = threadIdx.x;
    int w = tid >> 5, lane = tid & 31;

    {
        uint2 vh = ((const uint2*)(g_hhi[0] + b * HH))[tid];
        uint2 vl = ((const uint2*)(g_hlo[0] + b * HH))[tid];
        float2 h0 = unpack2h(vh.x), h1 = unpack2h(vh.y);
        float2 l0 = unpack2h(vl.x), l1 = unpack2h(vl.y);
        float4 f = make_float4(h0.x + l0.x, h0.y + l0.y, h1.x + l1.x, h1.y + l1.y);
        ((float4*)sh)[tid] = f;
    }
    __syncthreads();

#pragma unroll
    for (int cc = 0; cc < 8; cc++) {
        int c = w * 8 + cc;
        float s = 0.f;
        if (c < CC) {
            const float* wr = fcw + c * HH;
#pragma unroll 8
            for (int i = 0; i < 32; i++) {
                int k = i * 32 + lane;
                s += sh[k] * wr[k];
            }
        }
#pragma unroll
        for (int off = 16; off > 0; off >>= 1) s += __shfl_xor_sync(0xFFFFFFFF, s, off);
        if (lane == 0) sl[c] = (c < CC) ? s + fcb[c] : -1e30f;
    }
    __syncthreads();

    if (w == 0) {
        float v0 = sl[lane], v1 = sl[lane + 32];
        float m = fmaxf(v0, v1);
#pragma unroll
        for (int off = 16; off > 0; off >>= 1) m = fmaxf(m, __shfl_xor_sync(0xFFFFFFFF, m, off));
        float e = expf(v0 - m) + expf(v1 - m);
#pragma unroll
        for (int off = 16; off > 0; off >>= 1) e += __shfl_xor_sync(0xFFFFFFFF, e, off);
        if (lane == 0) { s_red[0] = m; s_red[1] = logf(e); }
    }
    __syncthreads();
    if (tid < CC) out[b * CC + tid] = sl[tid] - s_red[0] - s_red[1];
}

// ---------------------------------------------------------------------------
extern "C" void kernel_launch(void* const* d_in, const int* in_sizes, int n_in,
                              void* d_out, int out_size) {
    const float* inp = (const float*)d_in[0];   // [B,T,I]
    const float* Wih = (const float*)d_in[1];   // [4H,I]
    const float* Whh = (const float*)d_in[2];   // [4H,H]
    const float* bih = (const float*)d_in[3];   // [4H]
    const float* bhh = (const float*)d_in[4];   // [4H]
    const float* fcw = (const float*)d_in[5];   // [C,H]
    const float* fcb = (const float*)d_in[6];   // [C]
    float* out = (float*)d_out;                 // [B,C]

    cudaFuncSetAttribute(lstm_kernel, cudaFuncAttributeMaxDynamicSharedMemorySize, SMEM_DYN);
    cudaFuncSetAttribute(xproj_mma_kernel, cudaFuncAttributeMaxDynamicSharedMemorySize, SMEM_X);

    zero_kernel<<<512, 256>>>();
    conv_kernel<<<1024, 256>>>(inp, Wih);

    dim3 gx(64, 16);
    xproj_mma_kernel<<<gx, 256, SMEM_X>>>(bih, bhh);

    lstm_kernel<<<NCTA, 256, SMEM_DYN>>>(Whh);

    fc_kernel<<<BB, 64 * 4>>>(fcw, fcb, out);
}

// round 17
// speedup vs baseline: 1.9369x; 1.2517x over previous
#include <cuda_runtime.h>
#include <cuda_bf16.h>
#include <cuda_fp16.h>
#include <math.h>
#include <cstdint>

// Problem dims
constexpr int BB = 64;    // batch
constexpr int TT = 256;   // time steps
constexpr int II = 256;   // input dim
constexpr int HH = 1024;  // hidden
constexpr int CC = 60;    // classes
constexpr int NCTA = 128; // persistent CTAs; each owns 8 h-cols x 4 gates = 32 gate cols

// Dynamic SMEM layout (lstm_kernel)
constexpr int A_B = 0;         // 128KB: full h, 64 rows x 2048B, block-swizzled
                               // overlays: exchange 4 x 9216B at [0..36864);
                               //           x-tile 32KB at [65536..98304)
constexpr int XT = 65536;      // x tile: 64 rows x 512B, block-swizzled
constexpr int WF = 131072;     // 64KB fragment-direct W_hh (fp16)
constexpr int WX = 196608;     // 16KB fragment-direct W_ih (fp16)
constexpr int SMEM_DYN = 212992;

// Scratch (__device__ globals: allocation-free)
__device__ __half g_hhi[2][BB * HH];              // h (fp16), ping-pong
__device__ __half g_hlo[2][BB * HH];              // h lo correction (final step only)
__device__ __half g_xh[BB * TT * II];             // inputs fp16  [(b*T+t)][i]
__device__ unsigned g_cnt[8];                     // striped step counters

// ---------------------------------------------------------------------------
// helpers
// ---------------------------------------------------------------------------
__device__ __forceinline__ uint32_t smem_u32(const void* p) {
    uint32_t a;
    asm("{ .reg .u64 t; cvta.to.shared.u64 t, %1; cvt.u32.u64 %0, t; }" : "=r"(a) : "l"(p));
    return a;
}
__device__ __forceinline__ void ldm_x4(uint32_t* r, uint32_t addr) {
    asm volatile("ldmatrix.sync.aligned.m8n8.x4.shared.b16 {%0,%1,%2,%3}, [%4];"
                 : "=r"(r[0]), "=r"(r[1]), "=r"(r[2]), "=r"(r[3]) : "r"(addr));
}
__device__ __forceinline__ void mma_f16(float* d, const uint32_t* a, uint32_t b0, uint32_t b1) {
    asm volatile(
        "mma.sync.aligned.m16n8k16.row.col.f32.f16.f16.f32 "
        "{%0,%1,%2,%3}, {%4,%5,%6,%7}, {%8,%9}, {%0,%1,%2,%3};"
        : "+f"(d[0]), "+f"(d[1]), "+f"(d[2]), "+f"(d[3])
        : "r"(a[0]), "r"(a[1]), "r"(a[2]), "r"(a[3]), "r"(b0), "r"(b1));
}
__device__ __forceinline__ uint32_t pack2h(__half a, __half b) {
    return (uint32_t)*(uint16_t*)&a | ((uint32_t)*(uint16_t*)&b << 16);
}
__device__ __forceinline__ float2 unpack2h(uint32_t v) {
    __half2 h = *(__half2*)&v;
    return __half22float2(h);
}
__device__ __forceinline__ void poll_ge(const unsigned* p, unsigned tgt) {
    unsigned v;
    do {
        asm volatile("ld.acquire.gpu.global.u32 %0, [%1];" : "=r"(v) : "l"(p) : "memory");
    } while (v < tgt);
}
// HW tanh: single MUFU op (sm_75+); sigmoid via tanh identity (1 MUFU + 1 FFMA)
__device__ __forceinline__ float ftanh(float x) {
    float y;
    asm("tanh.approx.f32 %0, %1;" : "=f"(y) : "f"(x));
    return y;
}
__device__ __forceinline__ float fsigmoid(float x) {
    return fmaf(ftanh(0.5f * x), 0.5f, 0.5f);
}

// ---------------------------------------------------------------------------
// Zero-init h buffers + striped step counters.
// ---------------------------------------------------------------------------
__global__ void zero_kernel() {
    int i = blockIdx.x * blockDim.x + threadIdx.x;
    if (i < BB * HH) {            // u32 words cover both ping-pong buffers
        ((unsigned*)g_hhi)[i] = 0u;
        ((unsigned*)g_hlo)[i] = 0u;
    }
    if (i < 8) g_cnt[i] = 0u;
}

// ---------------------------------------------------------------------------
// Convert inputs to fp16 (row-major, same layout).
// ---------------------------------------------------------------------------
__global__ void conv_kernel(const float* __restrict__ inp) {
    int stride = gridDim.x * blockDim.x;
    int i0 = blockIdx.x * blockDim.x + threadIdx.x;
    for (int i = i0; i < 1048576; i += stride) {       // inputs: 1M float4
        float4 v = ((const float4*)inp)[i];
        uint2 h = make_uint2(pack2h(__float2half(v.x), __float2half(v.y)),
                             pack2h(__float2half(v.z), __float2half(v.w)));
        ((uint2*)g_xh)[i] = h;
    }
}

// ---------------------------------------------------------------------------
// Persistent fused LSTM: 128 CTAs x 256 thr, fp16 single-term.
// gates = h @ W_hh^T + x_t @ W_ih^T + bias.  The x-term runs BEFORE the
// barrier poll each step (h-independent), accumulating into the same
// per-warp accumulators; K effectively 1280 split as 4 kh x (256h + 64x).
// R13 warp tile (rg in 0..1: 32 rows; kh in 0..3), cooperative h staging.
// ---------------------------------------------------------------------------
__global__ __launch_bounds__(256, 1) void lstm_kernel(
    const float* __restrict__ Whh, const float* __restrict__ Wih,
    const float* __restrict__ bih, const float* __restrict__ bhh) {
    extern __shared__ char sm[];
    const int tid = threadIdx.x;
    const int lane = tid & 31;
    const int w = tid >> 5;
    const int rg = w >> 2, kh = w & 3;
    const int hc0 = blockIdx.x * 8;
    const uint32_t smb = smem_u32(sm);

    // ---- one-time: W_hh fragment fill (fp16, fragment-direct layout) ----
    for (int idx = tid; idx < 16384; idx += 256) {
        int r = idx & 3, ln = (idx >> 2) & 31, ks = (idx >> 7) & 63, nhh = idx >> 13;
        int nt = r >> 1;
        int kk = (r & 1) * 8 + (ln & 3) * 2;
        int nl = nhh * 16 + nt * 8 + (ln >> 2);
        int k = ks * 16 + kk;
        int gr = (nl >> 3) * 1024 + hc0 + (nl & 7);
        __half h0 = __float2half(Whh[gr * 1024 + k]);
        __half h1 = __float2half(Whh[gr * 1024 + k + 1]);
        ((uint32_t*)(sm + WF))[idx] = pack2h(h0, h1);
    }
    // ---- one-time: W_ih fragment fill (K=256, 16 ksteps) ----
    for (int idx = tid; idx < 4096; idx += 256) {
        int r = idx & 3, ln = (idx >> 2) & 31, ks = (idx >> 7) & 15, nhh = idx >> 11;
        int nt = r >> 1;
        int kk = (r & 1) * 8 + (ln & 3) * 2;
        int nl = nhh * 16 + nt * 8 + (ln >> 2);
        int k = ks * 16 + kk;
        int gr = (nl >> 3) * 1024 + hc0 + (nl & 7);
        float2 wv = *(const float2*)(Wih + gr * II + k);
        ((uint32_t*)(sm + WX))[idx] = pack2h(__float2half(wv.x), __float2half(wv.y));
    }
    __syncthreads();

    // A/X ldmatrix per-lane constants
    const int ar0 = rg * 32 + (lane & 15);
    const int ar1 = ar0 + 16;
    const int ahalf = lane >> 4;

    // W fragment bases (uint4 idx = nhh*2048 + ks*32 + lane)
    const uint4* wf0 = (const uint4*)(sm + WF) + (kh * 16) * 32 + lane;
    const uint4* wf1 = wf0 + 2048;
    // W_ih fragment bases (uint4 idx = nhh*512 + ks*32 + lane), ks0 = kh*4
    const uint4* wx0 = (const uint4*)(sm + WX) + (kh * 4) * 32 + lane;
    const uint4* wx1 = wx0 + 512;

    // epilogue ownership + bias registers
    const int eb = tid & 63, ej = tid >> 6;
    float biasv[8];
#pragma unroll
    for (int q = 0; q < 4; q++) {
#pragma unroll
        for (int st = 0; st < 2; st++) {
            int g = q * 1024 + hc0 + ej + st * 4;
            biasv[q * 2 + st] = bih[g] + bhh[g];
        }
    }
    float c0 = 0.f, c1 = 0.f;

    for (int t = 0; t < TT; t++) {
        const uint4* gh = (const uint4*)g_hhi[t & 1];

        // ---- stage x tile (64 rows x 512B) into XT: h-independent ----
#pragma unroll
        for (int i = 0; i < 8; i++) {
            int s = i * 256 + tid;
            int row = s >> 5, seg = s & 31;
            uint4 v = __ldcg((const uint4*)g_xh + ((size_t)row * TT + t) * 32 + seg);
            *(uint4*)(sm + XT + row * 512 + (seg >> 3) * 128 + (((seg & 7) ^ (row & 7)) << 4)) = v;
        }
        __syncthreads();

        // ---- x-MMA: 4 ksteps of this warp's 64-k slice ----
        float acc[8][4];
#pragma unroll
        for (int z = 0; z < 8; z++)
#pragma unroll
            for (int r = 0; r < 4; r++) acc[z][r] = 0.f;
#pragma unroll
        for (int kl = 0; kl < 4; kl++) {
            int seg = kh * 8 + kl * 2 + ahalf;
            int block = seg >> 3, inner = seg & 7;
            uint32_t a0[4], a1[4];
            ldm_x4(a0, smb + XT + ar0 * 512 + block * 128 + ((inner ^ (ar0 & 7)) << 4));
            ldm_x4(a1, smb + XT + ar1 * 512 + block * 128 + ((inner ^ (ar1 & 7)) << 4));
            uint4 b0 = wx0[kl * 32];
            uint4 b1 = wx1[kl * 32];
            mma_f16(acc[0], a0, b0.x, b0.y);
            mma_f16(acc[1], a0, b0.z, b0.w);
            mma_f16(acc[2], a0, b1.x, b1.y);
            mma_f16(acc[3], a0, b1.z, b1.w);
            mma_f16(acc[4], a1, b0.x, b0.y);
            mma_f16(acc[5], a1, b0.z, b0.w);
            mma_f16(acc[6], a1, b1.x, b1.y);
            mma_f16(acc[7], a1, b1.z, b1.w);
        }

        // ---- wait for all CTAs' step t-1 (each warp polls) ----
        if (t) {
            if (lane < 8) poll_ge(&g_cnt[lane], 16u * (unsigned)t);
            __syncwarp();
        }
        __syncthreads();   // all x-MMA reads of XT done before h staging clobbers

        // ---- cooperative h staging: full 128KB, 32 uint4/thread (proven) ----
#pragma unroll
        for (int i0 = 0; i0 < 32; i0 += 8) {
            uint4 v[8];
#pragma unroll
            for (int i = 0; i < 8; i++) v[i] = __ldcg(gh + (i0 + i) * 256 + tid);
#pragma unroll
            for (int i = 0; i < 8; i++) {
                int s = (i0 + i) * 256 + tid;
                int row = s >> 7, seg = s & 127;
                int block = seg >> 3, inner = seg & 7;
                *(uint4*)(sm + A_B + row * 2048 + block * 128 + ((inner ^ (row & 7)) << 4)) = v[i];
            }
        }
        __syncthreads();

        // ---- h-MMA: 16 ksteps of this warp's 256-k chunk ----
#pragma unroll
        for (int kl = 0; kl < 16; kl++) {
            int seg = kh * 32 + kl * 2 + ahalf;
            int block = seg >> 3, inner = seg & 7;
            uint32_t a0[4], a1[4];
            ldm_x4(a0, smb + A_B + ar0 * 2048 + block * 128 + ((inner ^ (ar0 & 7)) << 4));
            ldm_x4(a1, smb + A_B + ar1 * 2048 + block * 128 + ((inner ^ (ar1 & 7)) << 4));
            uint4 b0 = wf0[kl * 32];
            uint4 b1 = wf1[kl * 32];
            mma_f16(acc[0], a0, b0.x, b0.y);
            mma_f16(acc[1], a0, b0.z, b0.w);
            mma_f16(acc[2], a0, b1.x, b1.y);
            mma_f16(acc[3], a0, b1.z, b1.w);
            mma_f16(acc[4], a1, b0.x, b0.y);
            mma_f16(acc[5], a1, b0.z, b0.w);
            mma_f16(acc[6], a1, b1.x, b1.y);
            mma_f16(acc[7], a1, b1.z, b1.w);
        }
        __syncthreads();   // A reads done -> safe to overlay exchange regions

        // ---- exchange: write partials to region kh  [32 cols][stride 72] ----
        {
            float* sgk = (float*)(sm + kh * 9216);
            int grp = lane >> 2, tg = lane & 3;
#pragma unroll
            for (int nj = 0; nj < 4; nj++) {
                int col = nj * 8 + tg * 2;
                int row0 = rg * 32 + grp;
                int row1 = row0 + 16;
                sgk[col * 72 + row0] = acc[nj][0];
                sgk[(col + 1) * 72 + row0] = acc[nj][1];
                sgk[col * 72 + row0 + 8] = acc[nj][2];
                sgk[(col + 1) * 72 + row0 + 8] = acc[nj][3];
                sgk[col * 72 + row1] = acc[4 + nj][0];
                sgk[(col + 1) * 72 + row1] = acc[4 + nj][1];
                sgk[col * 72 + row1 + 8] = acc[4 + nj][2];
                sgk[(col + 1) * 72 + row1 + 8] = acc[4 + nj][3];
            }
        }
        __syncthreads();

        // ---- pointwise (HW tanh): sum 4 k-partials + bias; 2 states/thread ----
        {
            const float* s0 = (const float*)(sm);
            const float* s1 = (const float*)(sm + 9216);
            const float* s2 = (const float*)(sm + 18432);
            const float* s3 = (const float*)(sm + 27648);
            __half* hh = g_hhi[(t + 1) & 1];
            __half* hl = g_hlo[(t + 1) & 1];
            const bool last = (t == TT - 1);
#pragma unroll
            for (int st = 0; st < 2; st++) {
                int j = ej + st * 4;
                int o0 = (0 + j) * 72 + eb, o1 = (8 + j) * 72 + eb;
                int o2 = (16 + j) * 72 + eb, o3 = (24 + j) * 72 + eb;
                float iv = s0[o0] + s1[o0] + s2[o0] + s3[o0] + biasv[0 * 2 + st];
                float fv = s0[o1] + s1[o1] + s2[o1] + s3[o1] + biasv[1 * 2 + st];
                float gv = s0[o2] + s1[o2] + s2[o2] + s3[o2] + biasv[2 * 2 + st];
                float ov = s0[o3] + s1[o3] + s2[o3] + s3[o3] + biasv[3 * 2 + st];
                float& cs = st ? c1 : c0;
                float cn = fsigmoid(fv) * cs + fsigmoid(iv) * ftanh(gv);
                cs = cn;
                float hn = fsigmoid(ov) * ftanh(cn);
                __half hbb = __float2half(hn);
                hh[eb * HH + hc0 + j] = hbb;
                if (last) hl[eb * HH + hc0 + j] = __float2half(hn - __half2float(hbb));
            }
        }
        __syncthreads();
        if (tid == 0) {
            __threadfence();                           // order h stores (gpu scope)
            atomicAdd(&g_cnt[blockIdx.x & 7], 1u);     // striped step-done signal
        }
    }
}

// ---------------------------------------------------------------------------
// logits = h_last @ fc_w^T + fc_b; out = log_softmax.  grid=64, block=256.
// h_last = g_hhi[0] + g_hlo[0]  (full precision at the final step)
// ---------------------------------------------------------------------------
__global__ __launch_bounds__(256) void fc_kernel(const float* __restrict__ fcw,
                                                 const float* __restrict__ fcb,
                                                 float* __restrict__ out) {
    __shared__ float sh[HH];
    __shared__ float sl[64];
    __shared__ float s_red[2];
    int b = blockIdx.x;
    int tid = threadIdx.x;
    int w = tid >> 5, lane = tid & 31;

    {
        uint2 vh = ((const uint2*)(g_hhi[0] + b * HH))[tid];
        uint2 vl = ((const uint2*)(g_hlo[0] + b * HH))[tid];
        float2 h0 = unpack2h(vh.x), h1 = unpack2h(vh.y);
        float2 l0 = unpack2h(vl.x), l1 = unpack2h(vl.y);
        float4 f = make_float4(h0.x + l0.x, h0.y + l0.y, h1.x + l1.x, h1.y + l1.y);
        ((float4*)sh)[tid] = f;
    }
    __syncthreads();

#pragma unroll
    for (int cc = 0; cc < 8; cc++) {
        int c = w * 8 + cc;
        float s = 0.f;
        if (c < CC) {
            const float* wr = fcw + c * HH;
#pragma unroll 8
            for (int i = 0; i < 32; i++) {
                int k = i * 32 + lane;
                s += sh[k] * wr[k];
            }
        }
#pragma unroll
        for (int off = 16; off > 0; off >>= 1) s += __shfl_xor_sync(0xFFFFFFFF, s, off);
        if (lane == 0) sl[c] = (c < CC) ? s + fcb[c] : -1e30f;
    }
    __syncthreads();

    if (w == 0) {
        float v0 = sl[lane], v1 = sl[lane + 32];
        float m = fmaxf(v0, v1);
#pragma unroll
        for (int off = 16; off > 0; off >>= 1) m = fmaxf(m, __shfl_xor_sync(0xFFFFFFFF, m, off));
        float e = expf(v0 - m) + expf(v1 - m);
#pragma unroll
        for (int off = 16; off > 0; off >>= 1) e += __shfl_xor_sync(0xFFFFFFFF, e, off);
        if (lane == 0) { s_red[0] = m; s_red[1] = logf(e); }
    }
    __syncthreads();
    if (tid < CC) out[b * CC + tid] = sl[tid] - s_red[0] - s_red[1];
}

// ---------------------------------------------------------------------------
extern "C" void kernel_launch(void* const* d_in, const int* in_sizes, int n_in,
                              void* d_out, int out_size) {
    const float* inp = (const float*)d_in[0];   // [B,T,I]
    const float* Wih = (const float*)d_in[1];   // [4H,I]
    const float* Whh = (const float*)d_in[2];   // [4H,H]
    const float* bih = (const float*)d_in[3];   // [4H]
    const float* bhh = (const float*)d_in[4];   // [4H]
    const float* fcw = (const float*)d_in[5];   // [C,H]
    const float* fcb = (const float*)d_in[6];   // [C]
    float* out = (float*)d_out;                 // [B,C]

    cudaFuncSetAttribute(lstm_kernel, cudaFuncAttributeMaxDynamicSharedMemorySize, SMEM_DYN);

    zero_kernel<<<512, 256>>>();
    conv_kernel<<<512, 256>>>(inp);

    lstm_kernel<<<NCTA, 256, SMEM_DYN>>>(Whh, Wih, bih, bhh);

    fc_kernel<<<BB, 64 * 4>>>(fcw, fcb, out);
}